// round 13
// baseline (speedup 1.0000x reference)
#include <cuda_runtime.h>
#include <cuda_bf16.h>
#include <math.h>

// HumanPoseModule: fused 6D-rot -> FK -> axis-angle
// d_in[0] = glb_reduced_6d (BT,10,6) f32   rows: joints [1,2,3,6,9,12,13,14,16,17]
// d_in[1] = orientation_6d (BT,6,6)  f32   rows: joints [0,4,5,15,18,19]
// out      = (BT,24,3) f32
//
// Packed f32x2: each lane handles its joint for TWO samples; warp covers 4.
// Direct per-lane global gathers (good warp-level locality), packed FFMA2
// compute, compact smem output staging with coalesced float4 writeback.

typedef unsigned long long u64;

__device__ __forceinline__ u64 f2pack(float lo, float hi) {
    u64 r; asm("mov.b64 %0, {%1, %2};" : "=l"(r) : "f"(lo), "f"(hi)); return r;
}
__device__ __forceinline__ float f2lo(u64 v) {
    float lo, hi; asm("mov.b64 {%0, %1}, %2;" : "=f"(lo), "=f"(hi) : "l"(v)); return lo;
}
__device__ __forceinline__ float f2hi(u64 v) {
    float lo, hi; asm("mov.b64 {%0, %1}, %2;" : "=f"(lo), "=f"(hi) : "l"(v)); return hi;
}
__device__ __forceinline__ u64 f2mul(u64 a, u64 b) {
    u64 r; asm("mul.rn.f32x2 %0, %1, %2;" : "=l"(r) : "l"(a), "l"(b)); return r;
}
__device__ __forceinline__ u64 f2add(u64 a, u64 b) {
    u64 r; asm("add.rn.f32x2 %0, %1, %2;" : "=l"(r) : "l"(a), "l"(b)); return r;
}
__device__ __forceinline__ u64 f2fma(u64 a, u64 b, u64 c) {
    u64 r; asm("fma.rn.f32x2 %0, %1, %2, %3;" : "=l"(r) : "l"(a), "l"(b), "l"(c)); return r;
}
__device__ __forceinline__ u64 f2rsqrt(u64 a) {
    return f2pack(rsqrtf(f2lo(a)), rsqrtf(f2hi(a)));
}

#define F2_NEG1 0xBF800000BF800000ULL   /* (-1.0f, -1.0f) */
#define F2_ONE  0x3F8000003F800000ULL   /* ( 1.0f,  1.0f) */

// a - b, single rounding (== sub.rn)
__device__ __forceinline__ u64 f2sub(u64 a, u64 b) {
    return f2fma(b, F2_NEG1, a);
}

// packed Gram-Schmidt 6d -> rotation matrix (rows)
__device__ __forceinline__ void rot6d_f2(const u64* d6, u64* m) {
    u64 a1x = d6[0], a1y = d6[1], a1z = d6[2];
    u64 a2x = d6[3], a2y = d6[4], a2z = d6[5];
    u64 n1 = f2fma(a1x, a1x, f2fma(a1y, a1y, f2mul(a1z, a1z)));
    u64 r1 = f2rsqrt(n1);
    u64 b1x = f2mul(a1x, r1), b1y = f2mul(a1y, r1), b1z = f2mul(a1z, r1);
    u64 d = f2fma(b1x, a2x, f2fma(b1y, a2y, f2mul(b1z, a2z)));
    u64 dn = f2mul(d, F2_NEG1);
    u64 b2x = f2fma(dn, b1x, a2x);
    u64 b2y = f2fma(dn, b1y, a2y);
    u64 b2z = f2fma(dn, b1z, a2z);
    u64 n2 = f2fma(b2x, b2x, f2fma(b2y, b2y, f2mul(b2z, b2z)));
    u64 r2 = f2rsqrt(n2);
    b2x = f2mul(b2x, r2); b2y = f2mul(b2y, r2); b2z = f2mul(b2z, r2);
    m[0] = b1x; m[1] = b1y; m[2] = b1z;
    m[3] = b2x; m[4] = b2y; m[5] = b2z;
    m[6] = f2sub(f2mul(b1y, b2z), f2mul(b1z, b2y));
    m[7] = f2sub(f2mul(b1z, b2x), f2mul(b1x, b2z));
    m[8] = f2sub(f2mul(b1x, b2y), f2mul(b1y, b2x));
}

// atan(a) for a in [0,1], minimax poly (abs err ~1e-6 rad)
__device__ __forceinline__ float fast_atan01(float a) {
    float s = a * a;
    float r = -0.0117212f;
    r = fmaf(r, s, 0.05265332f);
    r = fmaf(r, s, -0.11643287f);
    r = fmaf(r, s, 0.19354346f);
    r = fmaf(r, s, -0.33262347f);
    r = fmaf(r, s, 0.99997726f);
    return r * a;
}

// scalar tail: argmax pivot + axis-angle from precomputed candidate terms.
// Small-angle branch removed (general formula converges; rel gap ~1e-12 at the
// 1e-6 threshold; exact 0 at n == 0 in both formulations).
__device__ __forceinline__ void aa_tail(float t0, float t1, float t2, float t3,
                                        float d21, float d02, float d10,
                                        float s10, float s02, float s21,
                                        float* __restrict__ aa) {
    float best = t0; int idx = 0;
    if (t1 > best) { best = t1; idx = 1; }
    if (t2 > best) { best = t2; idx = 2; }
    if (t3 > best) { best = t3; idx = 3; }

    float w, x, y, z;   // UNscaled quaternion (positive multiple of reference's)
    if (idx == 0)      { w = best; x = d21;  y = d02;  z = d10; }
    else if (idx == 1) { w = d21;  x = best; y = s10;  z = s02; }
    else if (idx == 2) { w = d02;  x = s10;  y = best; z = s21; }
    else               { w = d10;  x = s02;  y = s21;  z = best; }

    float sb = rsqrtf(best);                 // best >= 1 always (sum t = 4)

    float nsq = x * x + y * y + z * z;
    float rn = rsqrtf(fmaxf(nsq, 1e-30f));   // 1/n
    float n = nsq * rn;

    // half = atan2(n, w): scale-invariant
    float aw = fabsf(w);
    float mn = fminf(n, aw), mx = fmaxf(n, aw);
    float a = __fdividef(mn, mx);
    float r = fast_atan01(a);
    if (n > aw) r = 1.5707963267948966f - r;
    if (w < 0.0f) r = 3.14159265358979323f - r;

    // sin(half) = n/hyp; out = x*k, k = (0.5*sb)*(2r)*hyp*rn = r*hyp*rn*sb
    float hsq = fmaf(w, w, nsq);
    float hyp = hsq * rsqrtf(hsq);
    float k = r * hyp * rn * sb;
    aa[0] = x * k;
    aa[1] = y * k;
    aa[2] = z * k;
}

// dual matrix -> axis-angle: packed linear front, scalar branchy tail per half
__device__ __forceinline__ void mat_to_aa_dual(const u64* m,
                                               float* __restrict__ aaA,
                                               float* __restrict__ aaB) {
    u64 A = f2add(m[0], m[4]);       // m00+m11
    u64 B = f2sub(m[0], m[4]);       // m00-m11
    u64 C = f2add(m[8], F2_ONE);     // m22+1
    u64 D = f2sub(m[8], F2_ONE);     // m22-1
    u64 t0 = f2add(A, C);
    u64 t1 = f2sub(B, D);
    u64 t2 = f2mul(f2add(B, D), F2_NEG1);
    u64 t3 = f2sub(C, A);
    u64 d21 = f2sub(m[7], m[5]);
    u64 d02 = f2sub(m[2], m[6]);
    u64 d10 = f2sub(m[3], m[1]);
    u64 s10 = f2add(m[3], m[1]);
    u64 s02 = f2add(m[2], m[6]);
    u64 s21 = f2add(m[5], m[7]);

    aa_tail(f2lo(t0), f2lo(t1), f2lo(t2), f2lo(t3),
            f2lo(d21), f2lo(d02), f2lo(d10),
            f2lo(s10), f2lo(s02), f2lo(s21), aaA);
    aa_tail(f2hi(t0), f2hi(t1), f2hi(t2), f2hi(t3),
            f2hi(d21), f2hi(d02), f2hi(d10),
            f2hi(s10), f2hi(s02), f2hi(s21), aaB);
}

__global__ __launch_bounds__(256, 7)
void pose_kernel(const float* __restrict__ glb, const float* __restrict__ ori,
                 float* __restrict__ outp, int n) {
    // per-warp staging: 4 samples * 72 floats
    __shared__ float stage[8][288];

    int l = threadIdx.x & 31;
    int warp_in_block = threadIdx.x >> 5;
    int w = (blockIdx.x * blockDim.x + threadIdx.x) >> 5;   // global warp id
    int slot = l & 15;       // joint slot
    int pair = l >> 4;       // which sample-pair in the warp

    if (w * 4 >= n) return;
    int p0 = w * 4 + pair * 2;
    int pa = min(p0, n - 1);
    int pb = min(p0 + 1, n - 1);

    // ---- packed lookup tables (no local memory) ----
    bool is_ori = (0xC831u >> slot) & 1u;                              // slots {0,4,5,11,14,15}
    int row = (int)((0x5498376543212100ULL >> (slot * 4)) & 15);       // row in source array
    int pl  = (int)((0xDCA9877763210000ULL >> (slot * 4)) & 15);       // parent's slot
    int out_j = slot + (slot >= 8 ? 4 : (slot == 7 ? 2 : 0));          // output joint index

    const float* Sa = is_ori ? (ori + (size_t)pa * 36 + row * 6)
                             : (glb + (size_t)pa * 60 + row * 6);
    const float* Sb = is_ori ? (ori + (size_t)pb * 36 + row * 6)
                             : (glb + (size_t)pb * 60 + row * 6);

    u64 d6[6];
    {
        float2 a0 = *reinterpret_cast<const float2*>(Sa);
        float2 a1 = *reinterpret_cast<const float2*>(Sa + 2);
        float2 a2 = *reinterpret_cast<const float2*>(Sa + 4);
        float2 b0 = *reinterpret_cast<const float2*>(Sb);
        float2 b1 = *reinterpret_cast<const float2*>(Sb + 2);
        float2 b2 = *reinterpret_cast<const float2*>(Sb + 4);
        d6[0] = f2pack(a0.x, b0.x); d6[1] = f2pack(a0.y, b0.y);
        d6[2] = f2pack(a1.x, b1.x); d6[3] = f2pack(a1.y, b1.y);
        d6[4] = f2pack(a2.x, b2.x); d6[5] = f2pack(a2.y, b2.y);
    }

    u64 X[9];
    rot6d_f2(d6, X);

    // L = Xp^T * X (packed). Slots 0-3 (parent = root): L = X exactly
    // (slot0 -> root itself; slots 1-3: root^T root = I elimination).
    bool root_parent = (slot < 4);
    u64 L[9];
#pragma unroll
    for (int i = 0; i < 3; i++) {
        u64 xp0 = __shfl_sync(0xffffffffu, X[0 * 3 + i], pl, 16);
        u64 xp1 = __shfl_sync(0xffffffffu, X[1 * 3 + i], pl, 16);
        u64 xp2 = __shfl_sync(0xffffffffu, X[2 * 3 + i], pl, 16);
#pragma unroll
        for (int j = 0; j < 3; j++) {
            u64 v = f2fma(xp0, X[0 * 3 + j],
                    f2fma(xp1, X[1 * 3 + j],
                    f2mul(xp2, X[2 * 3 + j])));
            L[i * 3 + j] = root_parent ? X[i * 3 + j] : v;
        }
    }

    float aaA[3], aaB[3];
    mat_to_aa_dual(L, aaA, aaB);

    // ---- stage into smem ----
    float* ws = stage[warp_in_block];
    int qA = pair * 2, qB = qA + 1;
    {
        float* dA = ws + qA * 72 + out_j * 3;
        dA[0] = aaA[0]; dA[1] = aaA[1]; dA[2] = aaA[2];
        float* dB = ws + qB * 72 + out_j * 3;
        dB[0] = aaB[0]; dB[1] = aaB[1]; dB[2] = aaB[2];
    }
    // zero ignored joints {7,8,10,11,20,21,22,23} for both samples
    if (slot < 8) {
        int ign = slot + (slot < 2 ? 7 : (slot < 4 ? 8 : 16));
        float* zA = ws + qA * 72 + ign * 3;
        zA[0] = 0.0f; zA[1] = 0.0f; zA[2] = 0.0f;
        float* zB = ws + qB * 72 + ign * 3;
        zB[0] = 0.0f; zB[1] = 0.0f; zB[2] = 0.0f;
    }
    __syncwarp();

    // ---- coalesced float4 writeback: up to 72 float4 per warp (4 samples) ----
    {
        int rem = min(n - w * 4, 4);
        int nf4 = rem * 18;
        const float4* s4 = reinterpret_cast<const float4*>(ws);
        float4* dst4 = reinterpret_cast<float4*>(outp + (size_t)w * 288);
        for (int i = l; i < nf4; i += 32)
            dst4[i] = s4[i];
    }
}

extern "C" void kernel_launch(void* const* d_in, const int* in_sizes, int n_in,
                              void* d_out, int out_size) {
    const float* glb = (const float*)d_in[0];
    const float* ori = (const float*)d_in[1];
    float* outp = (float*)d_out;
    int n = in_sizes[0] / 60;                       // BT samples
    long long warps = ((long long)n + 3) / 4;       // 4 samples per warp
    int blocks = (int)((warps + 7) / 8);            // 8 warps per block
    pose_kernel<<<blocks, 256>>>(glb, ori, outp, n);
}

// round 14
// speedup vs baseline: 1.1875x; 1.1875x over previous
#include <cuda_runtime.h>
#include <cuda_bf16.h>
#include <math.h>

// HumanPoseModule: fused 6D-rot -> FK -> axis-angle
// d_in[0] = glb_reduced_6d (BT,10,6) f32   rows: joints [1,2,3,6,9,12,13,14,16,17]
// d_in[1] = orientation_6d (BT,6,6)  f32   rows: joints [0,4,5,15,18,19]
// out      = (BT,24,3) f32
//
// Packed f32x2: each lane handles its joint for TWO samples; warp covers 4.
// Direct per-lane global gathers, packed FFMA2 compute, smem output staging.
// Round-11 structure (40 regs / 6 blocks/SM sweet spot) + dual-packed atan poly.

typedef unsigned long long u64;

__device__ __forceinline__ u64 f2pack(float lo, float hi) {
    u64 r; asm("mov.b64 %0, {%1, %2};" : "=l"(r) : "f"(lo), "f"(hi)); return r;
}
__device__ __forceinline__ float f2lo(u64 v) {
    float lo, hi; asm("mov.b64 {%0, %1}, %2;" : "=f"(lo), "=f"(hi) : "l"(v)); return lo;
}
__device__ __forceinline__ float f2hi(u64 v) {
    float lo, hi; asm("mov.b64 {%0, %1}, %2;" : "=f"(lo), "=f"(hi) : "l"(v)); return hi;
}
__device__ __forceinline__ u64 f2mul(u64 a, u64 b) {
    u64 r; asm("mul.rn.f32x2 %0, %1, %2;" : "=l"(r) : "l"(a), "l"(b)); return r;
}
__device__ __forceinline__ u64 f2add(u64 a, u64 b) {
    u64 r; asm("add.rn.f32x2 %0, %1, %2;" : "=l"(r) : "l"(a), "l"(b)); return r;
}
__device__ __forceinline__ u64 f2fma(u64 a, u64 b, u64 c) {
    u64 r; asm("fma.rn.f32x2 %0, %1, %2, %3;" : "=l"(r) : "l"(a), "l"(b), "l"(c)); return r;
}
__device__ __forceinline__ u64 f2rsqrt(u64 a) {
    return f2pack(rsqrtf(f2lo(a)), rsqrtf(f2hi(a)));
}

#define F2_NEG1 0xBF800000BF800000ULL   /* (-1.0f, -1.0f) */
#define F2_ONE  0x3F8000003F800000ULL   /* ( 1.0f,  1.0f) */

// a - b, single rounding (== sub.rn)
__device__ __forceinline__ u64 f2sub(u64 a, u64 b) {
    return f2fma(b, F2_NEG1, a);
}

__device__ __forceinline__ u64 f2const(float c) {
    unsigned int b = __float_as_uint(c);
    return ((u64)b << 32) | b;
}

// packed Gram-Schmidt 6d -> rotation matrix (rows)
__device__ __forceinline__ void rot6d_f2(const u64* d6, u64* m) {
    u64 a1x = d6[0], a1y = d6[1], a1z = d6[2];
    u64 a2x = d6[3], a2y = d6[4], a2z = d6[5];
    u64 n1 = f2fma(a1x, a1x, f2fma(a1y, a1y, f2mul(a1z, a1z)));
    u64 r1 = f2rsqrt(n1);
    u64 b1x = f2mul(a1x, r1), b1y = f2mul(a1y, r1), b1z = f2mul(a1z, r1);
    u64 d = f2fma(b1x, a2x, f2fma(b1y, a2y, f2mul(b1z, a2z)));
    u64 dn = f2mul(d, F2_NEG1);
    u64 b2x = f2fma(dn, b1x, a2x);
    u64 b2y = f2fma(dn, b1y, a2y);
    u64 b2z = f2fma(dn, b1z, a2z);
    u64 n2 = f2fma(b2x, b2x, f2fma(b2y, b2y, f2mul(b2z, b2z)));
    u64 r2 = f2rsqrt(n2);
    b2x = f2mul(b2x, r2); b2y = f2mul(b2y, r2); b2z = f2mul(b2z, r2);
    m[0] = b1x; m[1] = b1y; m[2] = b1z;
    m[3] = b2x; m[4] = b2y; m[5] = b2z;
    m[6] = f2sub(f2mul(b1y, b2z), f2mul(b1z, b2y));
    m[7] = f2sub(f2mul(b1z, b2x), f2mul(b1x, b2z));
    m[8] = f2sub(f2mul(b1x, b2y), f2mul(b1y, b2x));
}

// per-half front: argmax pivot + everything up to the atan argument
struct AaMid {
    float x, y, z;     // unscaled quaternion vector part
    float w, n;        // scalar part, |vec|
    float sb, rn, nsq; // rsqrt(best), 1/n, n^2
    float a;           // atan argument in [0,1]
};

__device__ __forceinline__ AaMid aa_front(float t0, float t1, float t2, float t3,
                                          float d21, float d02, float d10,
                                          float s10, float s02, float s21) {
    float best = t0; int idx = 0;
    if (t1 > best) { best = t1; idx = 1; }
    if (t2 > best) { best = t2; idx = 2; }
    if (t3 > best) { best = t3; idx = 3; }

    AaMid o;
    float w, x, y, z;
    if (idx == 0)      { w = best; x = d21;  y = d02;  z = d10; }
    else if (idx == 1) { w = d21;  x = best; y = s10;  z = s02; }
    else if (idx == 2) { w = d02;  x = s10;  y = best; z = s21; }
    else               { w = d10;  x = s02;  y = s21;  z = best; }

    o.w = w; o.x = x; o.y = y; o.z = z;
    o.sb = rsqrtf(best);                     // best >= 1 always (sum t = 4)
    o.nsq = x * x + y * y + z * z;
    o.rn = rsqrtf(fmaxf(o.nsq, 1e-30f));     // 1/n
    o.n = o.nsq * o.rn;
    float aw = fabsf(w);
    float mn = fminf(o.n, aw), mx = fmaxf(o.n, aw);
    o.a = __fdividef(mn, mx);
    return o;
}

// per-half back: quadrant fixups + k = r*hyp*rn*sb, write 3 outputs.
// Small-angle branch removed (general formula converges; rel gap ~1e-12 at the
// 1e-6 threshold; exact 0 at n == 0 in both formulations).
__device__ __forceinline__ void aa_back(const AaMid& o, float r,
                                        float* __restrict__ aa) {
    float aw = fabsf(o.w);
    if (o.n > aw) r = 1.5707963267948966f - r;
    if (o.w < 0.0f) r = 3.14159265358979323f - r;
    float hsq = fmaf(o.w, o.w, o.nsq);
    float hyp = hsq * rsqrtf(hsq);           // sin(half) = n/hyp
    float k = r * hyp * o.rn * o.sb;
    aa[0] = o.x * k;
    aa[1] = o.y * k;
    aa[2] = o.z * k;
}

// dual matrix -> axis-angle: packed linear front, scalar pivots, packed poly
__device__ __forceinline__ void mat_to_aa_dual(const u64* m,
                                               float* __restrict__ aaA,
                                               float* __restrict__ aaB) {
    u64 A = f2add(m[0], m[4]);       // m00+m11
    u64 B = f2sub(m[0], m[4]);       // m00-m11
    u64 C = f2add(m[8], F2_ONE);     // m22+1
    u64 D = f2sub(m[8], F2_ONE);     // m22-1
    u64 t0 = f2add(A, C);
    u64 t1 = f2sub(B, D);
    u64 t2 = f2mul(f2add(B, D), F2_NEG1);
    u64 t3 = f2sub(C, A);
    u64 d21 = f2sub(m[7], m[5]);
    u64 d02 = f2sub(m[2], m[6]);
    u64 d10 = f2sub(m[3], m[1]);
    u64 s10 = f2add(m[3], m[1]);
    u64 s02 = f2add(m[2], m[6]);
    u64 s21 = f2add(m[5], m[7]);

    AaMid oA = aa_front(f2lo(t0), f2lo(t1), f2lo(t2), f2lo(t3),
                        f2lo(d21), f2lo(d02), f2lo(d10),
                        f2lo(s10), f2lo(s02), f2lo(s21));
    AaMid oB = aa_front(f2hi(t0), f2hi(t1), f2hi(t2), f2hi(t3),
                        f2hi(d21), f2hi(d02), f2hi(d10),
                        f2hi(s10), f2hi(s02), f2hi(s21));

    // packed atan poly over both halves: same FMA sequence per half as scalar
    // fast_atan01 (abs err ~1e-6 rad on [0,1])
    u64 av = f2pack(oA.a, oB.a);
    u64 s = f2mul(av, av);
    u64 r = f2const(-0.0117212f);
    r = f2fma(r, s, f2const(0.05265332f));
    r = f2fma(r, s, f2const(-0.11643287f));
    r = f2fma(r, s, f2const(0.19354346f));
    r = f2fma(r, s, f2const(-0.33262347f));
    r = f2fma(r, s, f2const(0.99997726f));
    r = f2mul(r, av);

    aa_back(oA, f2lo(r), aaA);
    aa_back(oB, f2hi(r), aaB);
}

__global__ __launch_bounds__(256, 6)
void pose_kernel(const float* __restrict__ glb, const float* __restrict__ ori,
                 float* __restrict__ outp, int n) {
    // per-warp staging: 4 samples * 72 floats
    __shared__ float stage[8][288];

    int l = threadIdx.x & 31;
    int warp_in_block = threadIdx.x >> 5;
    int w = (blockIdx.x * blockDim.x + threadIdx.x) >> 5;   // global warp id
    int slot = l & 15;       // joint slot
    int pair = l >> 4;       // which sample-pair in the warp

    if (w * 4 >= n) return;
    int p0 = w * 4 + pair * 2;
    int pa = min(p0, n - 1);
    int pb = min(p0 + 1, n - 1);

    // ---- packed lookup tables (no local memory) ----
    bool is_ori = (0xC831u >> slot) & 1u;                              // slots {0,4,5,11,14,15}
    int row = (int)((0x5498376543212100ULL >> (slot * 4)) & 15);       // row in source array
    int pl  = (int)((0xDCA9877763210000ULL >> (slot * 4)) & 15);       // parent's slot
    int out_j = slot + (slot >= 8 ? 4 : (slot == 7 ? 2 : 0));          // output joint index

    const float* Sa = is_ori ? (ori + (size_t)pa * 36 + row * 6)
                             : (glb + (size_t)pa * 60 + row * 6);
    const float* Sb = is_ori ? (ori + (size_t)pb * 36 + row * 6)
                             : (glb + (size_t)pb * 60 + row * 6);

    u64 d6[6];
    {
        float2 a0 = *reinterpret_cast<const float2*>(Sa);
        float2 a1 = *reinterpret_cast<const float2*>(Sa + 2);
        float2 a2 = *reinterpret_cast<const float2*>(Sa + 4);
        float2 b0 = *reinterpret_cast<const float2*>(Sb);
        float2 b1 = *reinterpret_cast<const float2*>(Sb + 2);
        float2 b2 = *reinterpret_cast<const float2*>(Sb + 4);
        d6[0] = f2pack(a0.x, b0.x); d6[1] = f2pack(a0.y, b0.y);
        d6[2] = f2pack(a1.x, b1.x); d6[3] = f2pack(a1.y, b1.y);
        d6[4] = f2pack(a2.x, b2.x); d6[5] = f2pack(a2.y, b2.y);
    }

    u64 X[9];
    rot6d_f2(d6, X);

    // L = Xp^T * X (packed). Slots 0-3 (parent = root): L = X exactly
    // (slot0 -> root itself; slots 1-3: root^T root = I elimination).
    bool root_parent = (slot < 4);
    u64 L[9];
#pragma unroll
    for (int i = 0; i < 3; i++) {
        u64 xp0 = __shfl_sync(0xffffffffu, X[0 * 3 + i], pl, 16);
        u64 xp1 = __shfl_sync(0xffffffffu, X[1 * 3 + i], pl, 16);
        u64 xp2 = __shfl_sync(0xffffffffu, X[2 * 3 + i], pl, 16);
#pragma unroll
        for (int j = 0; j < 3; j++) {
            u64 v = f2fma(xp0, X[0 * 3 + j],
                    f2fma(xp1, X[1 * 3 + j],
                    f2mul(xp2, X[2 * 3 + j])));
            L[i * 3 + j] = root_parent ? X[i * 3 + j] : v;
        }
    }

    float aaA[3], aaB[3];
    mat_to_aa_dual(L, aaA, aaB);

    // ---- stage into smem ----
    float* ws = stage[warp_in_block];
    int qA = pair * 2, qB = qA + 1;
    {
        float* dA = ws + qA * 72 + out_j * 3;
        dA[0] = aaA[0]; dA[1] = aaA[1]; dA[2] = aaA[2];
        float* dB = ws + qB * 72 + out_j * 3;
        dB[0] = aaB[0]; dB[1] = aaB[1]; dB[2] = aaB[2];
    }
    // zero ignored joints {7,8,10,11,20,21,22,23} for both samples
    if (slot < 8) {
        int ign = slot + (slot < 2 ? 7 : (slot < 4 ? 8 : 16));
        float* zA = ws + qA * 72 + ign * 3;
        zA[0] = 0.0f; zA[1] = 0.0f; zA[2] = 0.0f;
        float* zB = ws + qB * 72 + ign * 3;
        zB[0] = 0.0f; zB[1] = 0.0f; zB[2] = 0.0f;
    }
    __syncwarp();

    // ---- coalesced float4 writeback: up to 72 float4 per warp (4 samples) ----
    {
        int rem = min(n - w * 4, 4);
        int nf4 = rem * 18;
        const float4* s4 = reinterpret_cast<const float4*>(ws);
        float4* dst4 = reinterpret_cast<float4*>(outp + (size_t)w * 288);
        for (int i = l; i < nf4; i += 32)
            dst4[i] = s4[i];
    }
}

extern "C" void kernel_launch(void* const* d_in, const int* in_sizes, int n_in,
                              void* d_out, int out_size) {
    const float* glb = (const float*)d_in[0];
    const float* ori = (const float*)d_in[1];
    float* outp = (float*)d_out;
    int n = in_sizes[0] / 60;                       // BT samples
    long long warps = ((long long)n + 3) / 4;       // 4 samples per warp
    int blocks = (int)((warps + 7) / 8);            // 8 warps per block
    pose_kernel<<<blocks, 256>>>(glb, ori, outp, n);
}

// round 15
// speedup vs baseline: 1.3003x; 1.0950x over previous
#include <cuda_runtime.h>
#include <cuda_bf16.h>
#include <math.h>

// HumanPoseModule: fused 6D-rot -> FK -> axis-angle
// d_in[0] = glb_reduced_6d (BT,10,6) f32   rows: joints [1,2,3,6,9,12,13,14,16,17]
// d_in[1] = orientation_6d (BT,6,6)  f32   rows: joints [0,4,5,15,18,19]
// out      = (BT,24,3) f32
//
// Packed f32x2: each lane handles its joint for TWO samples; warp covers 4.
// Direct per-lane global gathers, packed FFMA2 compute, smem output staging.
// Round-11 structure (40 regs / 6 blocks/SM sweet spot) + dual-packed atan poly.

typedef unsigned long long u64;

__device__ __forceinline__ u64 f2pack(float lo, float hi) {
    u64 r; asm("mov.b64 %0, {%1, %2};" : "=l"(r) : "f"(lo), "f"(hi)); return r;
}
__device__ __forceinline__ float f2lo(u64 v) {
    float lo, hi; asm("mov.b64 {%0, %1}, %2;" : "=f"(lo), "=f"(hi) : "l"(v)); return lo;
}
__device__ __forceinline__ float f2hi(u64 v) {
    float lo, hi; asm("mov.b64 {%0, %1}, %2;" : "=f"(lo), "=f"(hi) : "l"(v)); return hi;
}
__device__ __forceinline__ u64 f2mul(u64 a, u64 b) {
    u64 r; asm("mul.rn.f32x2 %0, %1, %2;" : "=l"(r) : "l"(a), "l"(b)); return r;
}
__device__ __forceinline__ u64 f2add(u64 a, u64 b) {
    u64 r; asm("add.rn.f32x2 %0, %1, %2;" : "=l"(r) : "l"(a), "l"(b)); return r;
}
__device__ __forceinline__ u64 f2fma(u64 a, u64 b, u64 c) {
    u64 r; asm("fma.rn.f32x2 %0, %1, %2, %3;" : "=l"(r) : "l"(a), "l"(b), "l"(c)); return r;
}
__device__ __forceinline__ u64 f2rsqrt(u64 a) {
    return f2pack(rsqrtf(f2lo(a)), rsqrtf(f2hi(a)));
}

#define F2_NEG1 0xBF800000BF800000ULL   /* (-1.0f, -1.0f) */
#define F2_ONE  0x3F8000003F800000ULL   /* ( 1.0f,  1.0f) */

// a - b, single rounding (== sub.rn)
__device__ __forceinline__ u64 f2sub(u64 a, u64 b) {
    return f2fma(b, F2_NEG1, a);
}

__device__ __forceinline__ u64 f2const(float c) {
    unsigned int b = __float_as_uint(c);
    return ((u64)b << 32) | b;
}

// packed Gram-Schmidt 6d -> rotation matrix (rows)
__device__ __forceinline__ void rot6d_f2(const u64* d6, u64* m) {
    u64 a1x = d6[0], a1y = d6[1], a1z = d6[2];
    u64 a2x = d6[3], a2y = d6[4], a2z = d6[5];
    u64 n1 = f2fma(a1x, a1x, f2fma(a1y, a1y, f2mul(a1z, a1z)));
    u64 r1 = f2rsqrt(n1);
    u64 b1x = f2mul(a1x, r1), b1y = f2mul(a1y, r1), b1z = f2mul(a1z, r1);
    u64 d = f2fma(b1x, a2x, f2fma(b1y, a2y, f2mul(b1z, a2z)));
    u64 dn = f2mul(d, F2_NEG1);
    u64 b2x = f2fma(dn, b1x, a2x);
    u64 b2y = f2fma(dn, b1y, a2y);
    u64 b2z = f2fma(dn, b1z, a2z);
    u64 n2 = f2fma(b2x, b2x, f2fma(b2y, b2y, f2mul(b2z, b2z)));
    u64 r2 = f2rsqrt(n2);
    b2x = f2mul(b2x, r2); b2y = f2mul(b2y, r2); b2z = f2mul(b2z, r2);
    m[0] = b1x; m[1] = b1y; m[2] = b1z;
    m[3] = b2x; m[4] = b2y; m[5] = b2z;
    m[6] = f2sub(f2mul(b1y, b2z), f2mul(b1z, b2y));
    m[7] = f2sub(f2mul(b1z, b2x), f2mul(b1x, b2z));
    m[8] = f2sub(f2mul(b1x, b2y), f2mul(b1y, b2x));
}

// per-half front: argmax pivot + everything up to the atan argument
struct AaMid {
    float x, y, z;     // unscaled quaternion vector part
    float w, n;        // scalar part, |vec|
    float sb, rn, nsq; // rsqrt(best), 1/n, n^2
    float a;           // atan argument in [0,1]
};

__device__ __forceinline__ AaMid aa_front(float t0, float t1, float t2, float t3,
                                          float d21, float d02, float d10,
                                          float s10, float s02, float s21) {
    float best = t0; int idx = 0;
    if (t1 > best) { best = t1; idx = 1; }
    if (t2 > best) { best = t2; idx = 2; }
    if (t3 > best) { best = t3; idx = 3; }

    AaMid o;
    float w, x, y, z;
    if (idx == 0)      { w = best; x = d21;  y = d02;  z = d10; }
    else if (idx == 1) { w = d21;  x = best; y = s10;  z = s02; }
    else if (idx == 2) { w = d02;  x = s10;  y = best; z = s21; }
    else               { w = d10;  x = s02;  y = s21;  z = best; }

    o.w = w; o.x = x; o.y = y; o.z = z;
    o.sb = rsqrtf(best);                     // best >= 1 always (sum t = 4)
    o.nsq = x * x + y * y + z * z;
    o.rn = rsqrtf(fmaxf(o.nsq, 1e-30f));     // 1/n
    o.n = o.nsq * o.rn;
    float aw = fabsf(w);
    float mn = fminf(o.n, aw), mx = fmaxf(o.n, aw);
    o.a = __fdividef(mn, mx);
    return o;
}

// per-half back: quadrant fixups + k = r*hyp*rn*sb, write 3 outputs.
// Small-angle branch removed (general formula converges; rel gap ~1e-12 at the
// 1e-6 threshold; exact 0 at n == 0 in both formulations).
__device__ __forceinline__ void aa_back(const AaMid& o, float r,
                                        float* __restrict__ aa) {
    float aw = fabsf(o.w);
    if (o.n > aw) r = 1.5707963267948966f - r;
    if (o.w < 0.0f) r = 3.14159265358979323f - r;
    float hsq = fmaf(o.w, o.w, o.nsq);
    float hyp = hsq * rsqrtf(hsq);           // sin(half) = n/hyp
    float k = r * hyp * o.rn * o.sb;
    aa[0] = o.x * k;
    aa[1] = o.y * k;
    aa[2] = o.z * k;
}

// dual matrix -> axis-angle: packed linear front, scalar pivots, packed poly
__device__ __forceinline__ void mat_to_aa_dual(const u64* m,
                                               float* __restrict__ aaA,
                                               float* __restrict__ aaB) {
    u64 A = f2add(m[0], m[4]);       // m00+m11
    u64 B = f2sub(m[0], m[4]);       // m00-m11
    u64 C = f2add(m[8], F2_ONE);     // m22+1
    u64 D = f2sub(m[8], F2_ONE);     // m22-1
    u64 t0 = f2add(A, C);
    u64 t1 = f2sub(B, D);
    u64 t2 = f2mul(f2add(B, D), F2_NEG1);
    u64 t3 = f2sub(C, A);
    u64 d21 = f2sub(m[7], m[5]);
    u64 d02 = f2sub(m[2], m[6]);
    u64 d10 = f2sub(m[3], m[1]);
    u64 s10 = f2add(m[3], m[1]);
    u64 s02 = f2add(m[2], m[6]);
    u64 s21 = f2add(m[5], m[7]);

    AaMid oA = aa_front(f2lo(t0), f2lo(t1), f2lo(t2), f2lo(t3),
                        f2lo(d21), f2lo(d02), f2lo(d10),
                        f2lo(s10), f2lo(s02), f2lo(s21));
    AaMid oB = aa_front(f2hi(t0), f2hi(t1), f2hi(t2), f2hi(t3),
                        f2hi(d21), f2hi(d02), f2hi(d10),
                        f2hi(s10), f2hi(s02), f2hi(s21));

    // packed atan poly over both halves: same FMA sequence per half as scalar
    // fast_atan01 (abs err ~1e-6 rad on [0,1])
    u64 av = f2pack(oA.a, oB.a);
    u64 s = f2mul(av, av);
    u64 r = f2const(-0.0117212f);
    r = f2fma(r, s, f2const(0.05265332f));
    r = f2fma(r, s, f2const(-0.11643287f));
    r = f2fma(r, s, f2const(0.19354346f));
    r = f2fma(r, s, f2const(-0.33262347f));
    r = f2fma(r, s, f2const(0.99997726f));
    r = f2mul(r, av);

    aa_back(oA, f2lo(r), aaA);
    aa_back(oB, f2hi(r), aaB);
}

__global__ __launch_bounds__(256, 6)
void pose_kernel(const float* __restrict__ glb, const float* __restrict__ ori,
                 float* __restrict__ outp, int n) {
    // per-warp staging: 4 samples * 72 floats
    __shared__ float stage[8][288];

    int l = threadIdx.x & 31;
    int warp_in_block = threadIdx.x >> 5;
    int w = (blockIdx.x * blockDim.x + threadIdx.x) >> 5;   // global warp id
    int slot = l & 15;       // joint slot
    int pair = l >> 4;       // which sample-pair in the warp

    if (w * 4 >= n) return;
    int p0 = w * 4 + pair * 2;
    int pa = min(p0, n - 1);
    int pb = min(p0 + 1, n - 1);

    // ---- packed lookup tables (no local memory) ----
    bool is_ori = (0xC831u >> slot) & 1u;                              // slots {0,4,5,11,14,15}
    int row = (int)((0x5498376543212100ULL >> (slot * 4)) & 15);       // row in source array
    int pl  = (int)((0xDCA9877763210000ULL >> (slot * 4)) & 15);       // parent's slot
    int out_j = slot + (slot >= 8 ? 4 : (slot == 7 ? 2 : 0));          // output joint index

    const float* Sa = is_ori ? (ori + (size_t)pa * 36 + row * 6)
                             : (glb + (size_t)pa * 60 + row * 6);
    const float* Sb = is_ori ? (ori + (size_t)pb * 36 + row * 6)
                             : (glb + (size_t)pb * 60 + row * 6);

    u64 d6[6];
    {
        float2 a0 = *reinterpret_cast<const float2*>(Sa);
        float2 a1 = *reinterpret_cast<const float2*>(Sa + 2);
        float2 a2 = *reinterpret_cast<const float2*>(Sa + 4);
        float2 b0 = *reinterpret_cast<const float2*>(Sb);
        float2 b1 = *reinterpret_cast<const float2*>(Sb + 2);
        float2 b2 = *reinterpret_cast<const float2*>(Sb + 4);
        d6[0] = f2pack(a0.x, b0.x); d6[1] = f2pack(a0.y, b0.y);
        d6[2] = f2pack(a1.x, b1.x); d6[3] = f2pack(a1.y, b1.y);
        d6[4] = f2pack(a2.x, b2.x); d6[5] = f2pack(a2.y, b2.y);
    }

    u64 X[9];
    rot6d_f2(d6, X);

    // L = Xp^T * X (packed). Slots 0-3 (parent = root): L = X exactly
    // (slot0 -> root itself; slots 1-3: root^T root = I elimination).
    bool root_parent = (slot < 4);
    u64 L[9];
#pragma unroll
    for (int i = 0; i < 3; i++) {
        u64 xp0 = __shfl_sync(0xffffffffu, X[0 * 3 + i], pl, 16);
        u64 xp1 = __shfl_sync(0xffffffffu, X[1 * 3 + i], pl, 16);
        u64 xp2 = __shfl_sync(0xffffffffu, X[2 * 3 + i], pl, 16);
#pragma unroll
        for (int j = 0; j < 3; j++) {
            u64 v = f2fma(xp0, X[0 * 3 + j],
                    f2fma(xp1, X[1 * 3 + j],
                    f2mul(xp2, X[2 * 3 + j])));
            L[i * 3 + j] = root_parent ? X[i * 3 + j] : v;
        }
    }

    float aaA[3], aaB[3];
    mat_to_aa_dual(L, aaA, aaB);

    // ---- stage into smem ----
    float* ws = stage[warp_in_block];
    int qA = pair * 2, qB = qA + 1;
    {
        float* dA = ws + qA * 72 + out_j * 3;
        dA[0] = aaA[0]; dA[1] = aaA[1]; dA[2] = aaA[2];
        float* dB = ws + qB * 72 + out_j * 3;
        dB[0] = aaB[0]; dB[1] = aaB[1]; dB[2] = aaB[2];
    }
    // zero ignored joints {7,8,10,11,20,21,22,23} for both samples
    if (slot < 8) {
        int ign = slot + (slot < 2 ? 7 : (slot < 4 ? 8 : 16));
        float* zA = ws + qA * 72 + ign * 3;
        zA[0] = 0.0f; zA[1] = 0.0f; zA[2] = 0.0f;
        float* zB = ws + qB * 72 + ign * 3;
        zB[0] = 0.0f; zB[1] = 0.0f; zB[2] = 0.0f;
    }
    __syncwarp();

    // ---- coalesced float4 writeback: up to 72 float4 per warp (4 samples) ----
    {
        int rem = min(n - w * 4, 4);
        int nf4 = rem * 18;
        const float4* s4 = reinterpret_cast<const float4*>(ws);
        float4* dst4 = reinterpret_cast<float4*>(outp + (size_t)w * 288);
        for (int i = l; i < nf4; i += 32)
            dst4[i] = s4[i];
    }
}

extern "C" void kernel_launch(void* const* d_in, const int* in_sizes, int n_in,
                              void* d_out, int out_size) {
    const float* glb = (const float*)d_in[0];
    const float* ori = (const float*)d_in[1];
    float* outp = (float*)d_out;
    int n = in_sizes[0] / 60;                       // BT samples
    long long warps = ((long long)n + 3) / 4;       // 4 samples per warp
    int blocks = (int)((warps + 7) / 8);            // 8 warps per block
    pose_kernel<<<blocks, 256>>>(glb, ori, outp, n);
}

// round 16
// speedup vs baseline: 1.3014x; 1.0008x over previous
#include <cuda_runtime.h>
#include <cuda_bf16.h>
#include <math.h>

// HumanPoseModule: fused 6D-rot -> FK -> axis-angle
// d_in[0] = glb_reduced_6d (BT,10,6) f32   rows: joints [1,2,3,6,9,12,13,14,16,17]
// d_in[1] = orientation_6d (BT,6,6)  f32   rows: joints [0,4,5,15,18,19]
// out      = (BT,24,3) f32
//
// Packed f32x2: each lane handles its joint for TWO samples; warp covers 4
// samples per iteration and loops twice (8 samples/warp) to amortize lane/table
// decode and base-pointer setup. Direct per-lane global gathers, packed FFMA2
// compute, smem output staging with coalesced float4 writeback.

typedef unsigned long long u64;

__device__ __forceinline__ u64 f2pack(float lo, float hi) {
    u64 r; asm("mov.b64 %0, {%1, %2};" : "=l"(r) : "f"(lo), "f"(hi)); return r;
}
__device__ __forceinline__ float f2lo(u64 v) {
    float lo, hi; asm("mov.b64 {%0, %1}, %2;" : "=f"(lo), "=f"(hi) : "l"(v)); return lo;
}
__device__ __forceinline__ float f2hi(u64 v) {
    float lo, hi; asm("mov.b64 {%0, %1}, %2;" : "=f"(lo), "=f"(hi) : "l"(v)); return hi;
}
__device__ __forceinline__ u64 f2mul(u64 a, u64 b) {
    u64 r; asm("mul.rn.f32x2 %0, %1, %2;" : "=l"(r) : "l"(a), "l"(b)); return r;
}
__device__ __forceinline__ u64 f2add(u64 a, u64 b) {
    u64 r; asm("add.rn.f32x2 %0, %1, %2;" : "=l"(r) : "l"(a), "l"(b)); return r;
}
__device__ __forceinline__ u64 f2fma(u64 a, u64 b, u64 c) {
    u64 r; asm("fma.rn.f32x2 %0, %1, %2, %3;" : "=l"(r) : "l"(a), "l"(b), "l"(c)); return r;
}
__device__ __forceinline__ u64 f2rsqrt(u64 a) {
    return f2pack(rsqrtf(f2lo(a)), rsqrtf(f2hi(a)));
}

#define F2_NEG1 0xBF800000BF800000ULL   /* (-1.0f, -1.0f) */
#define F2_ONE  0x3F8000003F800000ULL   /* ( 1.0f,  1.0f) */

// a - b, single rounding (== sub.rn)
__device__ __forceinline__ u64 f2sub(u64 a, u64 b) {
    return f2fma(b, F2_NEG1, a);
}

__device__ __forceinline__ u64 f2const(float c) {
    unsigned int b = __float_as_uint(c);
    return ((u64)b << 32) | b;
}

// packed Gram-Schmidt 6d -> rotation matrix (rows)
__device__ __forceinline__ void rot6d_f2(const u64* d6, u64* m) {
    u64 a1x = d6[0], a1y = d6[1], a1z = d6[2];
    u64 a2x = d6[3], a2y = d6[4], a2z = d6[5];
    u64 n1 = f2fma(a1x, a1x, f2fma(a1y, a1y, f2mul(a1z, a1z)));
    u64 r1 = f2rsqrt(n1);
    u64 b1x = f2mul(a1x, r1), b1y = f2mul(a1y, r1), b1z = f2mul(a1z, r1);
    u64 d = f2fma(b1x, a2x, f2fma(b1y, a2y, f2mul(b1z, a2z)));
    u64 dn = f2mul(d, F2_NEG1);
    u64 b2x = f2fma(dn, b1x, a2x);
    u64 b2y = f2fma(dn, b1y, a2y);
    u64 b2z = f2fma(dn, b1z, a2z);
    u64 n2 = f2fma(b2x, b2x, f2fma(b2y, b2y, f2mul(b2z, b2z)));
    u64 r2 = f2rsqrt(n2);
    b2x = f2mul(b2x, r2); b2y = f2mul(b2y, r2); b2z = f2mul(b2z, r2);
    m[0] = b1x; m[1] = b1y; m[2] = b1z;
    m[3] = b2x; m[4] = b2y; m[5] = b2z;
    m[6] = f2sub(f2mul(b1y, b2z), f2mul(b1z, b2y));
    m[7] = f2sub(f2mul(b1z, b2x), f2mul(b1x, b2z));
    m[8] = f2sub(f2mul(b1x, b2y), f2mul(b1y, b2x));
}

// per-half front: argmax pivot + everything up to the atan argument
struct AaMid {
    float x, y, z;     // unscaled quaternion vector part
    float w, n;        // scalar part, |vec|
    float sb, rn, nsq; // rsqrt(best), 1/n, n^2
    float a;           // atan argument in [0,1]
};

__device__ __forceinline__ AaMid aa_front(float t0, float t1, float t2, float t3,
                                          float d21, float d02, float d10,
                                          float s10, float s02, float s21) {
    float best = t0; int idx = 0;
    if (t1 > best) { best = t1; idx = 1; }
    if (t2 > best) { best = t2; idx = 2; }
    if (t3 > best) { best = t3; idx = 3; }

    AaMid o;
    float w, x, y, z;
    if (idx == 0)      { w = best; x = d21;  y = d02;  z = d10; }
    else if (idx == 1) { w = d21;  x = best; y = s10;  z = s02; }
    else if (idx == 2) { w = d02;  x = s10;  y = best; z = s21; }
    else               { w = d10;  x = s02;  y = s21;  z = best; }

    o.w = w; o.x = x; o.y = y; o.z = z;
    o.sb = rsqrtf(best);                     // best >= 1 always (sum t = 4)
    o.nsq = x * x + y * y + z * z;
    o.rn = rsqrtf(fmaxf(o.nsq, 1e-30f));     // 1/n
    o.n = o.nsq * o.rn;
    float aw = fabsf(w);
    float mn = fminf(o.n, aw), mx = fmaxf(o.n, aw);
    o.a = __fdividef(mn, mx);
    return o;
}

// per-half back: quadrant fixups + k = r*hyp*rn*sb, write 3 outputs.
// Small-angle branch removed (general formula converges; rel gap ~1e-12 at the
// 1e-6 threshold; exact 0 at n == 0 in both formulations).
__device__ __forceinline__ void aa_back(const AaMid& o, float r,
                                        float* __restrict__ aa) {
    float aw = fabsf(o.w);
    if (o.n > aw) r = 1.5707963267948966f - r;
    if (o.w < 0.0f) r = 3.14159265358979323f - r;
    float hsq = fmaf(o.w, o.w, o.nsq);
    float hyp = hsq * rsqrtf(hsq);           // sin(half) = n/hyp
    float k = r * hyp * o.rn * o.sb;
    aa[0] = o.x * k;
    aa[1] = o.y * k;
    aa[2] = o.z * k;
}

// dual matrix -> axis-angle: packed linear front, scalar pivots, packed poly
__device__ __forceinline__ void mat_to_aa_dual(const u64* m,
                                               float* __restrict__ aaA,
                                               float* __restrict__ aaB) {
    u64 A = f2add(m[0], m[4]);       // m00+m11
    u64 B = f2sub(m[0], m[4]);       // m00-m11
    u64 C = f2add(m[8], F2_ONE);     // m22+1
    u64 D = f2sub(m[8], F2_ONE);     // m22-1
    u64 t0 = f2add(A, C);
    u64 t1 = f2sub(B, D);
    u64 t2 = f2mul(f2add(B, D), F2_NEG1);
    u64 t3 = f2sub(C, A);
    u64 d21 = f2sub(m[7], m[5]);
    u64 d02 = f2sub(m[2], m[6]);
    u64 d10 = f2sub(m[3], m[1]);
    u64 s10 = f2add(m[3], m[1]);
    u64 s02 = f2add(m[2], m[6]);
    u64 s21 = f2add(m[5], m[7]);

    AaMid oA = aa_front(f2lo(t0), f2lo(t1), f2lo(t2), f2lo(t3),
                        f2lo(d21), f2lo(d02), f2lo(d10),
                        f2lo(s10), f2lo(s02), f2lo(s21));
    AaMid oB = aa_front(f2hi(t0), f2hi(t1), f2hi(t2), f2hi(t3),
                        f2hi(d21), f2hi(d02), f2hi(d10),
                        f2hi(s10), f2hi(s02), f2hi(s21));

    // packed atan poly over both halves: same FMA sequence per half as scalar
    // minimax atan on [0,1] (abs err ~1e-6 rad)
    u64 av = f2pack(oA.a, oB.a);
    u64 s = f2mul(av, av);
    u64 r = f2const(-0.0117212f);
    r = f2fma(r, s, f2const(0.05265332f));
    r = f2fma(r, s, f2const(-0.11643287f));
    r = f2fma(r, s, f2const(0.19354346f));
    r = f2fma(r, s, f2const(-0.33262347f));
    r = f2fma(r, s, f2const(0.99997726f));
    r = f2mul(r, av);

    aa_back(oA, f2lo(r), aaA);
    aa_back(oB, f2hi(r), aaB);
}

__global__ __launch_bounds__(256, 6)
void pose_kernel(const float* __restrict__ glb, const float* __restrict__ ori,
                 float* __restrict__ outp, int n) {
    // per-warp staging: 4 samples * 72 floats (reused across the 2 iterations)
    __shared__ float stage[8][288];

    int l = threadIdx.x & 31;
    int warp_in_block = threadIdx.x >> 5;
    int w = (blockIdx.x * blockDim.x + threadIdx.x) >> 5;   // global warp id
    int slot = l & 15;       // joint slot
    int pair = l >> 4;       // which sample-pair in the quad

    if (w * 8 >= n) return;

    // ---- per-warp constants, decoded ONCE for both iterations ----
    bool is_ori = (0xC831u >> slot) & 1u;                              // slots {0,4,5,11,14,15}
    int row = (int)((0x5498376543212100ULL >> (slot * 4)) & 15);       // row in source array
    int pl  = (int)((0xDCA9877763210000ULL >> (slot * 4)) & 15);       // parent's slot
    int out_j = slot + (slot >= 8 ? 4 : (slot == 7 ? 2 : 0));          // output joint index
    int ign = slot + (slot < 2 ? 7 : (slot < 4 ? 8 : 16));             // ignored joint (slots 0-7)
    bool root_parent = (slot < 4);

    const float* src_base = is_ori ? ori : glb;
    int stride = is_ori ? 36 : 60;
    int roff = row * 6;

    float* ws = stage[warp_in_block];
    int qA = pair * 2, qB = qA + 1;
    float* stA = ws + qA * 72;
    float* stB = ws + qB * 72;

#pragma unroll
    for (int it = 0; it < 2; it++) {
        int base = w * 8 + it * 4;            // warp-uniform
        if (base >= n) break;

        int p0 = base + pair * 2;
        int pa = min(p0, n - 1);
        int pb = min(p0 + 1, n - 1);

        const float* Sa = src_base + (size_t)pa * stride + roff;
        const float* Sb = src_base + (size_t)pb * stride + roff;

        u64 d6[6];
        {
            float2 a0 = *reinterpret_cast<const float2*>(Sa);
            float2 a1 = *reinterpret_cast<const float2*>(Sa + 2);
            float2 a2 = *reinterpret_cast<const float2*>(Sa + 4);
            float2 b0 = *reinterpret_cast<const float2*>(Sb);
            float2 b1 = *reinterpret_cast<const float2*>(Sb + 2);
            float2 b2 = *reinterpret_cast<const float2*>(Sb + 4);
            d6[0] = f2pack(a0.x, b0.x); d6[1] = f2pack(a0.y, b0.y);
            d6[2] = f2pack(a1.x, b1.x); d6[3] = f2pack(a1.y, b1.y);
            d6[4] = f2pack(a2.x, b2.x); d6[5] = f2pack(a2.y, b2.y);
        }

        u64 X[9];
        rot6d_f2(d6, X);

        // L = Xp^T * X (packed). Slots 0-3 (parent = root): L = X exactly
        // (slot0 -> root itself; slots 1-3: root^T root = I elimination).
        u64 L[9];
#pragma unroll
        for (int i = 0; i < 3; i++) {
            u64 xp0 = __shfl_sync(0xffffffffu, X[0 * 3 + i], pl, 16);
            u64 xp1 = __shfl_sync(0xffffffffu, X[1 * 3 + i], pl, 16);
            u64 xp2 = __shfl_sync(0xffffffffu, X[2 * 3 + i], pl, 16);
#pragma unroll
            for (int j = 0; j < 3; j++) {
                u64 v = f2fma(xp0, X[0 * 3 + j],
                        f2fma(xp1, X[1 * 3 + j],
                        f2mul(xp2, X[2 * 3 + j])));
                L[i * 3 + j] = root_parent ? X[i * 3 + j] : v;
            }
        }

        float aaA[3], aaB[3];
        mat_to_aa_dual(L, aaA, aaB);

        // ---- stage into smem ----
        {
            float* dA = stA + out_j * 3;
            dA[0] = aaA[0]; dA[1] = aaA[1]; dA[2] = aaA[2];
            float* dB = stB + out_j * 3;
            dB[0] = aaB[0]; dB[1] = aaB[1]; dB[2] = aaB[2];
        }
        // zero ignored joints {7,8,10,11,20,21,22,23} for both samples
        if (slot < 8) {
            float* zA = stA + ign * 3;
            zA[0] = 0.0f; zA[1] = 0.0f; zA[2] = 0.0f;
            float* zB = stB + ign * 3;
            zB[0] = 0.0f; zB[1] = 0.0f; zB[2] = 0.0f;
        }
        __syncwarp();

        // ---- coalesced float4 writeback: up to 72 float4 (4 samples) ----
        {
            int nf4 = min(n - base, 4) * 18;
            const float4* s4 = reinterpret_cast<const float4*>(ws);
            float4* dst4 = reinterpret_cast<float4*>(outp + (size_t)base * 72);
            for (int i = l; i < nf4; i += 32)
                dst4[i] = s4[i];
        }
        __syncwarp();   // WAR fence: writeback reads done before next-iter stores
    }
}

extern "C" void kernel_launch(void* const* d_in, const int* in_sizes, int n_in,
                              void* d_out, int out_size) {
    const float* glb = (const float*)d_in[0];
    const float* ori = (const float*)d_in[1];
    float* outp = (float*)d_out;
    int n = in_sizes[0] / 60;                       // BT samples
    long long warps = ((long long)n + 7) / 8;       // 8 samples per warp (2 quads)
    int blocks = (int)((warps + 7) / 8);            // 8 warps per block
    pose_kernel<<<blocks, 256>>>(glb, ori, outp, n);
}